// round 8
// baseline (speedup 1.0000x reference)
#include <cuda_runtime.h>

// inputs: float32 [16, 64, 256, 256] NCHW
#define NB      16
#define NC      64
#define HW4     16384                 // float4 per (n,c) slice
#define SLICE4  (NC * HW4)
#define TPB     256
#define EPS     1e-5f

#define NR      8                     // rounds (channel groups of 8)
#define CPR     8                     // channels per round
#define BPC     64                    // blocks per channel
#define NBLK    512                   // all co-resident (<= 148*4 slots)
#define ITERS   16                    // float4 per thread per tile (64 KB tile)

__device__ float g_sum[NC];
__device__ float g_sq [NC];
__device__ float g_scale[NC];         // rstd
__device__ float g_bias [NC];         // -mean*rstd
__device__ int   g_done [NC];         // per-channel reduce arrivals
__device__ int   g_ready[NC];         // per-channel stats published

__global__ void init_kernel() {
    const int t = threadIdx.x;
    if (t < NC) {
        g_sum[t] = 0.0f; g_sq[t] = 0.0f;
        g_done[t] = 0;   g_ready[t] = 0;
    }
}

// Reduce one 64 KB tile of channel c; fold into per-channel sums; the last
// arriving block of the channel finalizes scale/bias and raises ready[c].
__device__ __forceinline__ void reduce_tile(
    const float4* __restrict__ in, size_t base, int c,
    float* sh_s, float* sh_q, int tid, int lane, int wid)
{
    float s = 0.0f, q = 0.0f;
    {
        float4 v[8];
        #pragma unroll
        for (int k = 0; k < 8; k++) v[k] = in[base + k * TPB];
        #pragma unroll
        for (int k = 0; k < 8; k++) {
            s += (v[k].x + v[k].y) + (v[k].z + v[k].w);
            q += (v[k].x * v[k].x + v[k].y * v[k].y)
               + (v[k].z * v[k].z + v[k].w * v[k].w);
        }
        #pragma unroll
        for (int k = 0; k < 8; k++) v[k] = in[base + (k + 8) * TPB];
        #pragma unroll
        for (int k = 0; k < 8; k++) {
            s += (v[k].x + v[k].y) + (v[k].z + v[k].w);
            q += (v[k].x * v[k].x + v[k].y * v[k].y)
               + (v[k].z * v[k].z + v[k].w * v[k].w);
        }
    }

    #pragma unroll
    for (int off = 16; off > 0; off >>= 1) {
        s += __shfl_down_sync(0xffffffffu, s, off);
        q += __shfl_down_sync(0xffffffffu, q, off);
    }
    if (lane == 0) { sh_s[wid] = s; sh_q[wid] = q; }
    __syncthreads();

    if (tid == 0) {
        float ss = sh_s[0], qq = sh_q[0];
        #pragma unroll
        for (int w = 1; w < 8; w++) { ss += sh_s[w]; qq += sh_q[w]; }
        atomicAdd(&g_sum[c], ss);
        atomicAdd(&g_sq [c], qq);
        __threadfence();
        const int old = atomicAdd(&g_done[c], 1);
        if (old == BPC - 1) {
            __threadfence();
            const float invN = 1.0f / (float)(NB * HW4 * 4);
            const float mean = g_sum[c] * invN;
            const float rstd = rsqrtf(g_sq[c] * invN - mean * mean + EPS);
            g_scale[c] = rstd;
            g_bias [c] = -mean * rstd;
            __threadfence();
            atomicExch(&g_ready[c], 1);
        }
    }
    __syncthreads();   // sh_s/sh_q safe for reuse
}

__global__ void __launch_bounds__(TPB, 4)
fused_kernel(const float4* __restrict__ in, float4* __restrict__ out) {
    const int tid  = threadIdx.x;
    const int lane = tid & 31;
    const int wid  = tid >> 5;

    // Block -> tile: 64 blocks per channel; tile = quarter of one (n,c) slice.
    const int cidx = blockIdx.x >> 6;          // channel within round [0,8)
    const int b    = blockIdx.x & 63;
    const int n    = b >> 2;
    const int hw0  = (b & 3) * 4096;

    __shared__ float sh_s[8], sh_q[8];
    __shared__ float sh_sb[2];

    const size_t tbase = (size_t)n * SLICE4 + hw0 + tid;

    // ── pipeline fill: reduce round 0 ──
    {
        const int c0 = cidx;                   // round 0 channel
        reduce_tile(in, tbase + (size_t)c0 * HW4, c0, sh_s, sh_q, tid, lane, wid);
    }

    for (int g = 0; g < NR; g++) {
        const int c = g * CPR + cidx;

        // ── reduce next round first (hides the ready-wait below) ──
        if (g + 1 < NR) {
            const int cn = (g + 1) * CPR + cidx;
            reduce_tile(in, tbase + (size_t)cn * HW4, cn, sh_s, sh_q, tid, lane, wid);
        }

        // ── wait for my channel's stats (usually already set) ──
        if (tid == 0) {
            while (*((volatile int*)&g_ready[c]) == 0) __nanosleep(32);
            __threadfence();
            sh_sb[0] = g_scale[c];
            sh_sb[1] = g_bias [c];
        }
        __syncthreads();
        const float scale = sh_sb[0];
        const float bias  = sh_sb[1];

        // ── normalize my round-g tile; evict-first stores keep the output
        //    stream out of L2 so it can't evict the resident input ──
        const size_t base = tbase + (size_t)c * HW4;
        #pragma unroll
        for (int k = 0; k < ITERS; k++) {
            const size_t idx = base + k * TPB;
            float4 v = in[idx];
            float4 o;
            o.x = fmaf(v.x, scale, bias);
            o.y = fmaf(v.y, scale, bias);
            o.z = fmaf(v.z, scale, bias);
            o.w = fmaf(v.w, scale, bias);
            __stcs(&out[idx], o);
        }
        __syncthreads();   // sh_sb safe for next round
    }
}

extern "C" void kernel_launch(void* const* d_in, const int* in_sizes, int n_in,
                              void* d_out, int out_size) {
    const float4* in  = (const float4*)d_in[0];
    float4*       out = (float4*)d_out;

    init_kernel<<<1, 64>>>();
    fused_kernel<<<NBLK, TPB>>>(in, out);
}